// round 12
// baseline (speedup 1.0000x reference)
#include <cuda_runtime.h>
#include <cuda_fp16.h>
#include <math.h>
#include <stdint.h>

// ---------------- problem constants ----------------
#define BB    512
#define TT    64
#define EMBD  512
#define HIDD  1024
#define NG    4096
#define NOUT  2048
#define KIN   (EMBD + HIDD)     // 1536 (gates GEMM K: [x | h])
#define NCHUNK_G (KIN / 64)     // 24  (chunks 0..7 emb, 8..23 h)
#define NCHUNK_O (HIDD / 64)    // 16
#define NCTA  128               // 32 x 4 persistent grid
#define NSTAGE 4
#define SMEM_DYN (NSTAGE * 32768 + 256)

// ---------------- persistent device scratch ----------------
__device__ float g_bias[NG];                                      // interleaved b_ih+b_hh
__device__ __align__(16) __half g_h16[2][BB * HIDD];              // h (fp16), ping-pong
__device__ __align__(16) __half g_emb16[(size_t)TT * BB * EMBD];  // x_t (fp16), all steps
__device__ __align__(16) __half g_Wg[(size_t)NG * KIN];           // gate-interleaved rows [Wih|Whh]
__device__ __align__(16) __half g_Wo[(size_t)NOUT * HIDD];
__device__ unsigned g_cnt;                                        // grid barrier
__device__ volatile unsigned g_gen;

// ---------------- helpers ----------------
__device__ __forceinline__ uint32_t smem_u32(const void* p) {
    uint32_t a;
    asm("{ .reg .u64 t; cvta.to.shared.u64 t, %1; cvt.u32.u64 %0, t; }" : "=r"(a) : "l"(p));
    return a;
}
__device__ __forceinline__ void cp_async16(uint32_t dst, const void* src) {
    asm volatile("cp.async.cg.shared.global [%0], [%1], 16;" :: "r"(dst), "l"(src));
}
__device__ __forceinline__ void cp_commit() {
    asm volatile("cp.async.commit_group;" ::: "memory");
}
__device__ __forceinline__ void ldsm_x4(uint32_t* r, uint32_t addr) {
    asm volatile("ldmatrix.sync.aligned.m8n8.x4.shared.b16 {%0,%1,%2,%3}, [%4];"
                 : "=r"(r[0]), "=r"(r[1]), "=r"(r[2]), "=r"(r[3]) : "r"(addr));
}
__device__ __forceinline__ void mma16816(float* d, const uint32_t* a, uint32_t b0, uint32_t b1) {
    asm volatile(
        "mma.sync.aligned.m16n8k16.row.col.f32.f16.f16.f32 "
        "{%0,%1,%2,%3}, {%4,%5,%6,%7}, {%8,%9}, {%0,%1,%2,%3};"
        : "+f"(d[0]), "+f"(d[1]), "+f"(d[2]), "+f"(d[3])
        : "r"(a[0]), "r"(a[1]), "r"(a[2]), "r"(a[3]), "r"(b0), "r"(b1));
}
// fast activations via MUFU (rel err ~2e-7, no accuracy impact at our 4e-4 level)
__device__ __forceinline__ float fsig(float x)  { return __fdividef(1.0f, 1.0f + __expf(-x)); }
__device__ __forceinline__ float ftanh(float x) { return 1.0f - 2.0f * __fdividef(1.0f, 1.0f + __expf(2.0f * x)); }

// ---------------- setup kernels ----------------
__global__ void init_state_kernel() {
    int i = blockIdx.x * 256 + threadIdx.x;     // 524288 u32 = both h buffers
    ((uint32_t*)g_h16)[i] = 0u;
    if (i == 0) { g_cnt = 0; g_gen = 0; }
}

// interleaved bias: n' = 4u + gate
__global__ void bias_kernel(const float* __restrict__ b_ih, const float* __restrict__ b_hh) {
    int n_ = blockIdx.x * 256 + threadIdx.x;
    int gate = n_ & 3, j = n_ >> 2;
    g_bias[n_] = b_ih[gate * HIDD + j] + b_hh[gate * HIDD + j];
}

// W'g row n' = 4u+gate : [Wih(512) | Whh(1024)] fp16   (4 elems/thread)
__global__ void conv_wg_kernel(const float* __restrict__ W_ih, const float* __restrict__ W_hh) {
    int idx = blockIdx.x * 256 + threadIdx.x;   // NG*KIN/4
    int n_ = idx / (KIN / 4), k4 = (idx - n_ * (KIN / 4)) * 4;
    int gate = n_ & 3, j = n_ >> 2;
    int orig = gate * HIDD + j;
    float4 w = (k4 < EMBD) ? *(const float4*)&W_ih[(size_t)orig * EMBD + k4]
                           : *(const float4*)&W_hh[(size_t)orig * HIDD + (k4 - EMBD)];
    __half2 h0 = __floats2half2_rn(w.x, w.y);
    __half2 h1 = __floats2half2_rn(w.z, w.w);
    *(uint2*)&g_Wg[(size_t)n_ * KIN + k4] = make_uint2(*(uint32_t*)&h0, *(uint32_t*)&h1);
}

__global__ void conv_wo_kernel(const float* __restrict__ W_out) {
    int idx = blockIdx.x * 256 + threadIdx.x;   // NOUT*HIDD/4
    float4 w = *(const float4*)&W_out[(size_t)idx * 4];
    __half2 h0 = __floats2half2_rn(w.x, w.y);
    __half2 h1 = __floats2half2_rn(w.z, w.w);
    *(uint2*)&g_Wo[(size_t)idx * 4] = make_uint2(*(uint32_t*)&h0, *(uint32_t*)&h1);
}

// Precompute x_t (fp16) for all steps (4 elems/thread)
__global__ void emb_precompute_kernel(const int* __restrict__ tok, const float* __restrict__ emb) {
    size_t idx = (size_t)blockIdx.x * 256 + threadIdx.x;   // TT*BB*EMBD/4
    int t = (int)(idx / (BB * EMBD / 4));
    int rem = (int)(idx - (size_t)t * (BB * EMBD / 4));
    int b = rem / (EMBD / 4), k4 = (rem - b * (EMBD / 4)) * 4;
    float4 v = *(const float4*)&emb[(size_t)tok[b * TT + t] * EMBD + k4];
    __half2 h0 = __floats2half2_rn(v.x, v.y);
    __half2 h1 = __floats2half2_rn(v.z, v.w);
    *(uint2*)&g_emb16[((size_t)t * BB + b) * EMBD + k4] = make_uint2(*(uint32_t*)&h0, *(uint32_t*)&h1);
}

// ---------------- persistent LSTM kernel: all 64 steps ----------------
// CTA (bn, bm): batch rows [bm*128,+128), interleaved gate cols [bn*128,+128) = units [bn*32,+32).
// c kept in registers across all steps. Grid barrier deferred: x-chunks (0..7) of each step
// are computed before waiting for the previous step's h.
__global__ __launch_bounds__(256, 1) void lstm_persistent_kernel() {
    extern __shared__ char dyn[];
    const uint32_t sbase = (smem_u32(dyn) + 127u) & ~127u;
    __half* hs = (__half*)(dyn + (sbase - smem_u32(dyn)));   // h stage = stage-0 region

    const int tid  = threadIdx.x;
    const int wid  = tid >> 5, lane = tid & 31;
    const int m0 = blockIdx.y * 128, n0 = blockIdx.x * 128;
    const int w_m = (wid >> 2) * 64;
    const int w_n = (wid & 3) * 32;

    // loader mapping
    const int lr  = tid >> 3;
    const int lsB = (tid & 7) * 16;

    // ldmatrix lane offsets (pre-swizzle)
    const int q  = lane >> 3;
    const int r8 = lane & 7;
    const uint32_t arow = (uint32_t)(w_m + (q & 1) * 8 + r8);
    const uint32_t akb  = (uint32_t)((q >> 1) * 16);
    const uint32_t brow = (uint32_t)(w_n + (q >> 1) * 8 + r8);
    const uint32_t bkb  = (uint32_t)((q & 1) * 16);

    // per-thread bias (constant across steps)
    const int lcol = (lane & 3) * 2;
    float bj0[4], bj1[4];
#pragma unroll
    for (int nj = 0; nj < 4; nj++) {
        int col = n0 + w_n + nj * 8 + lcol;
        bj0[nj] = g_bias[col];
        bj1[nj] = g_bias[col + 1];
    }

    const int lrow = lane >> 2;
    const bool evenlane = (lane & 1) == 0;
    const int ul_base = (w_n >> 2) + ((lane & 3) >> 1);   // + nj*2

    float c_reg[4][4];
#pragma unroll
    for (int i = 0; i < 4; i++)
#pragma unroll
        for (int j = 0; j < 4; j++) c_reg[i][j] = 0.0f;

    for (int t = 0; t < TT; t++) {
        const __half* Ah = g_h16[t & 1];

        auto issue = [&](int kc) {
            const uint32_t st = sbase + (kc & (NSTAGE - 1)) * 32768;
            const __half* ag;
            size_t klda;
            if (kc < 8) {
                ag = g_emb16 + ((size_t)t * BB + (m0 + lr)) * EMBD + kc * 64 + (lsB >> 1);
                klda = EMBD;
            } else {
                ag = Ah + (size_t)(m0 + lr) * HIDD + (kc - 8) * 64 + (lsB >> 1);
                klda = HIDD;
            }
            const __half* bg = g_Wg + (size_t)(n0 + lr) * KIN + kc * 64 + (lsB >> 1);
#pragma unroll
            for (int i = 0; i < 4; i++) {
                uint32_t off = (uint32_t)(lr + i * 32) * 128u + (uint32_t)lsB;
                uint32_t sw  = off ^ ((off >> 3) & 0x70u);
                cp_async16(st + sw, ag + (size_t)i * 32 * klda);
                cp_async16(st + 16384 + sw, bg + (size_t)i * 32 * KIN);
            }
            cp_commit();
        };

        float acc[4][4][4];
#pragma unroll
        for (int i = 0; i < 4; i++)
#pragma unroll
            for (int j = 0; j < 4; j++)
#pragma unroll
                for (int v = 0; v < 4; v++) acc[i][j][v] = 0.0f;

        issue(0); issue(1); issue(2);          // all x-chunks: no barrier dependency

        for (int kc = 0; kc < NCHUNK_G; kc++) {
            const int rem = NCHUNK_G - 1 - kc;
            if (rem >= 2)      asm volatile("cp.async.wait_group 2;" ::: "memory");
            else if (rem == 1) asm volatile("cp.async.wait_group 1;" ::: "memory");
            else               asm volatile("cp.async.wait_group 0;" ::: "memory");
            __syncthreads();

            const int nx = kc + 3;
            if (nx < NCHUNK_G && nx != 8) issue(nx);

            const uint32_t stA = sbase + (kc & (NSTAGE - 1)) * 32768;
            const uint32_t stB = stA + 16384;

#pragma unroll
            for (int kk = 0; kk < 4; kk++) {
                uint32_t afr[4][4];
#pragma unroll
                for (int mi = 0; mi < 4; mi++) {
                    uint32_t off = (arow + mi * 16) * 128u + kk * 32u + akb;
                    ldsm_x4(afr[mi], stA + (off ^ ((off >> 3) & 0x70u)));
                }
                uint32_t bfr[2][4];
#pragma unroll
                for (int nj2 = 0; nj2 < 2; nj2++) {
                    uint32_t off = (brow + nj2 * 16) * 128u + kk * 32u + bkb;
                    ldsm_x4(bfr[nj2], stB + (off ^ ((off >> 3) & 0x70u)));
                }
#pragma unroll
                for (int mi = 0; mi < 4; mi++)
#pragma unroll
                    for (int nj = 0; nj < 4; nj++)
                        mma16816(acc[mi][nj], afr[mi],
                                 bfr[nj >> 1][(nj & 1) * 2], bfr[nj >> 1][(nj & 1) * 2 + 1]);
            }

            if (nx == 8) {
                // deferred grid wait: h(t) must be fully written before loading it
                if (tid == 0) {
                    while (g_gen < (unsigned)t) __nanosleep(32);
                    __threadfence();
                }
                __syncthreads();
                issue(8);
            }
        }

        // ----- fused LSTM epilogue -----
#pragma unroll
        for (int mi = 0; mi < 4; mi++) {
#pragma unroll
            for (int nj = 0; nj < 4; nj++) {
                float a0 = acc[mi][nj][0] + bj0[nj];
                float a1 = acc[mi][nj][1] + bj1[nj];
                float a2 = acc[mi][nj][2] + bj0[nj];
                float a3 = acc[mi][nj][3] + bj1[nj];
                float p0 = __shfl_xor_sync(0xffffffffu, a0, 1);
                float p1 = __shfl_xor_sync(0xffffffffu, a1, 1);
                float p2 = __shfl_xor_sync(0xffffffffu, a2, 1);
                float p3 = __shfl_xor_sync(0xffffffffu, a3, 1);
                float i_, f_, g_, o_;
                int bl;
                if (evenlane) { i_ = a0; f_ = a1; g_ = p0; o_ = p1; bl = w_m + mi * 16 + lrow; }
                else          { i_ = p2; f_ = p3; g_ = a2; o_ = a3; bl = w_m + mi * 16 + lrow + 8; }
                int ul = ul_base + nj * 2;
                i_ = fsig(i_);
                f_ = fsig(f_);
                g_ = ftanh(g_);
                o_ = fsig(o_);
                float cn = f_ * c_reg[mi][nj] + i_ * g_;
                c_reg[mi][nj] = cn;
                hs[bl * 32 + ul] = __float2half(o_ * ftanh(cn));
            }
        }
        __syncthreads();

        // coalesced h store: 128 rows x 32 halves -> g_h16[(t+1)&1]
        __half* hdst = g_h16[(t + 1) & 1];
#pragma unroll
        for (int it = 0; it < 2; it++) {
            int i = tid + it * 256;            // 512 uint4
            int row = i >> 2, seg = i & 3;
            uint4 v = ((const uint4*)hs)[i];
            *(uint4*)(hdst + (size_t)(m0 + row) * HIDD + (n0 >> 2) + seg * 8) = v;
        }
        __syncthreads();

        // arrive (no wait here — wait is deferred into next step)
        if (tid == 0) {
            __threadfence();
            if (atomicAdd(&g_cnt, 1u) == NCTA - 1) {
                g_cnt = 0;
                __threadfence();
                g_gen = (unsigned)(t + 1);
            }
        }
    }
}

// ---------------- output projection GEMM (fp16 HMMA, f32 out) ----------------
__global__ __launch_bounds__(256, 1) void out_gemm(float* __restrict__ Cout,
                                                   const float* __restrict__ biasO) {
    extern __shared__ char dyn[];
    const uint32_t sbase = (smem_u32(dyn) + 127u) & ~127u;

    const int tid  = threadIdx.x;
    const int wid  = tid >> 5, lane = tid & 31;
    const int m0 = blockIdx.y * 128, n0 = blockIdx.x * 128;
    const int w_m = (wid >> 2) * 64;
    const int w_n = (wid & 3) * 32;

    const int lr  = tid >> 3;
    const int lsB = (tid & 7) * 16;
    const __half* Ah = g_h16[0];   // final h after 64 steps
    auto issue = [&](int kc) {
        const uint32_t st = sbase + (kc & (NSTAGE - 1)) * 32768;
        const __half* ag = Ah + (size_t)(m0 + lr) * HIDD + kc * 64 + (lsB >> 1);
        const __half* bg = g_Wo + (size_t)(n0 + lr) * HIDD + kc * 64 + (lsB >> 1);
#pragma unroll
        for (int i = 0; i < 4; i++) {
            uint32_t off = (uint32_t)(lr + i * 32) * 128u + (uint32_t)lsB;
            uint32_t sw  = off ^ ((off >> 3) & 0x70u);
            cp_async16(st + sw, ag + (size_t)i * 32 * HIDD);
            cp_async16(st + 16384 + sw, bg + (size_t)i * 32 * HIDD);
        }
        cp_commit();
    };

    const int q  = lane >> 3;
    const int r8 = lane & 7;
    const uint32_t arow = (uint32_t)(w_m + (q & 1) * 8 + r8);
    const uint32_t akb  = (uint32_t)((q >> 1) * 16);
    const uint32_t brow = (uint32_t)(w_n + (q >> 1) * 8 + r8);
    const uint32_t bkb  = (uint32_t)((q & 1) * 16);

    float acc[4][4][4];
#pragma unroll
    for (int i = 0; i < 4; i++)
#pragma unroll
        for (int j = 0; j < 4; j++)
#pragma unroll
            for (int v = 0; v < 4; v++) acc[i][j][v] = 0.0f;

    issue(0); issue(1); issue(2);

    for (int kc = 0; kc < NCHUNK_O; kc++) {
        const int rem = NCHUNK_O - 1 - kc;
        if (rem >= 2)      asm volatile("cp.async.wait_group 2;" ::: "memory");
        else if (rem == 1) asm volatile("cp.async.wait_group 1;" ::: "memory");
        else               asm volatile("cp.async.wait_group 0;" ::: "memory");
        __syncthreads();
        if (kc + 3 < NCHUNK_O) issue(kc + 3);

        const uint32_t stA = sbase + (kc & (NSTAGE - 1)) * 32768;
        const uint32_t stB = stA + 16384;

#pragma unroll
        for (int kk = 0; kk < 4; kk++) {
            uint32_t afr[4][4];
#pragma unroll
            for (int mi = 0; mi < 4; mi++) {
                uint32_t off = (arow + mi * 16) * 128u + kk * 32u + akb;
                ldsm_x4(afr[mi], stA + (off ^ ((off >> 3) & 0x70u)));
            }
            uint32_t bfr[2][4];
#pragma unroll
            for (int nj2 = 0; nj2 < 2; nj2++) {
                uint32_t off = (brow + nj2 * 16) * 128u + kk * 32u + bkb;
                ldsm_x4(bfr[nj2], stB + (off ^ ((off >> 3) & 0x70u)));
            }
#pragma unroll
            for (int mi = 0; mi < 4; mi++)
#pragma unroll
                for (int nj = 0; nj < 4; nj++)
                    mma16816(acc[mi][nj], afr[mi],
                             bfr[nj >> 1][(nj & 1) * 2], bfr[nj >> 1][(nj & 1) * 2 + 1]);
        }
    }

    const int lrow = lane >> 2;
    const int lcol = (lane & 3) * 2;
#pragma unroll
    for (int mi = 0; mi < 4; mi++) {
#pragma unroll
        for (int nj = 0; nj < 4; nj++) {
            int row0 = m0 + w_m + mi * 16 + lrow;
            int col  = n0 + w_n + nj * 8 + lcol;
            float b0 = __ldg(&biasO[col]), b1 = __ldg(&biasO[col + 1]);
            *(float2*)&Cout[(size_t)row0 * NOUT + col] =
                make_float2(acc[mi][nj][0] + b0, acc[mi][nj][1] + b1);
            *(float2*)&Cout[(size_t)(row0 + 8) * NOUT + col] =
                make_float2(acc[mi][nj][2] + b0, acc[mi][nj][3] + b1);
        }
    }
}

// ---------------- launch ----------------
extern "C" void kernel_launch(void* const* d_in, const int* in_sizes, int n_in,
                              void* d_out, int out_size) {
    const int*   m     = (const int*)  d_in[0];
    const float* emb   = (const float*)d_in[1];
    const float* W_ih  = (const float*)d_in[2];
    const float* W_hh  = (const float*)d_in[3];
    const float* b_ih  = (const float*)d_in[4];
    const float* b_hh  = (const float*)d_in[5];
    const float* W_out = (const float*)d_in[6];
    const float* b_out = (const float*)d_in[7];
    float* out = (float*)d_out;

    cudaFuncSetAttribute(lstm_persistent_kernel, cudaFuncAttributeMaxDynamicSharedMemorySize, SMEM_DYN);
    cudaFuncSetAttribute(out_gemm, cudaFuncAttributeMaxDynamicSharedMemorySize, SMEM_DYN);

    init_state_kernel<<<(2 * BB * HIDD / 2) / 256, 256>>>();
    bias_kernel<<<NG / 256, 256>>>(b_ih, b_hh);
    conv_wg_kernel<<<(NG * KIN / 4) / 256, 256>>>(W_ih, W_hh);
    conv_wo_kernel<<<(NOUT * HIDD / 4) / 256, 256>>>(W_out);
    emb_precompute_kernel<<<(unsigned)(((size_t)TT * BB * EMBD / 4) / 256), 256>>>(m, emb);

    lstm_persistent_kernel<<<dim3(32, 4), 256, SMEM_DYN>>>();
    out_gemm<<<dim3(NOUT / 128, BB / 128), 256, SMEM_DYN>>>(out, b_out);
}

// round 13
// speedup vs baseline: 1.3924x; 1.3924x over previous
#include <cuda_runtime.h>
#include <cuda_fp16.h>
#include <math.h>
#include <stdint.h>

// ---------------- problem constants ----------------
#define BB    512
#define TT    64
#define EMBD  512
#define HIDD  1024
#define NG    4096
#define NOUT  2048
#define KIN   (EMBD + HIDD)     // 1536 (gates GEMM K: [x | h])
#define NCHUNK_G (KIN / 64)     // 24  (chunks 0..7 emb, 8..23 h)
#define NCHUNK_O (HIDD / 64)    // 16
#define NCTA  128               // 32 x 4 persistent grid
#define SMEM_DYN (3 * 32768 + 256)

// ---------------- persistent device scratch ----------------
__device__ float g_bias[NG];                                      // interleaved b_ih+b_hh
__device__ __align__(16) __half g_h16[2][BB * HIDD];              // h (fp16), ping-pong
__device__ __align__(16) __half g_emb16[(size_t)TT * BB * EMBD];  // x_t (fp16), all steps
__device__ __align__(16) __half g_Wg[(size_t)NG * KIN];           // gate-interleaved rows [Wih|Whh]
__device__ __align__(16) __half g_Wo[(size_t)NOUT * HIDD];
__device__ unsigned g_cnt;                                        // grid barrier
__device__ volatile unsigned g_gen;

// ---------------- helpers ----------------
__device__ __forceinline__ uint32_t smem_u32(const void* p) {
    uint32_t a;
    asm("{ .reg .u64 t; cvta.to.shared.u64 t, %1; cvt.u32.u64 %0, t; }" : "=r"(a) : "l"(p));
    return a;
}
__device__ __forceinline__ void cp_async16(uint32_t dst, const void* src) {
    asm volatile("cp.async.cg.shared.global [%0], [%1], 16;" :: "r"(dst), "l"(src));
}
__device__ __forceinline__ void cp_commit() {
    asm volatile("cp.async.commit_group;" ::: "memory");
}
__device__ __forceinline__ void ldsm_x4(uint32_t* r, uint32_t addr) {
    asm volatile("ldmatrix.sync.aligned.m8n8.x4.shared.b16 {%0,%1,%2,%3}, [%4];"
                 : "=r"(r[0]), "=r"(r[1]), "=r"(r[2]), "=r"(r[3]) : "r"(addr));
}
__device__ __forceinline__ void mma16816(float* d, const uint32_t* a, uint32_t b0, uint32_t b1) {
    asm volatile(
        "mma.sync.aligned.m16n8k16.row.col.f32.f16.f16.f32 "
        "{%0,%1,%2,%3}, {%4,%5,%6,%7}, {%8,%9}, {%0,%1,%2,%3};"
        : "+f"(d[0]), "+f"(d[1]), "+f"(d[2]), "+f"(d[3])
        : "r"(a[0]), "r"(a[1]), "r"(a[2]), "r"(a[3]), "r"(b0), "r"(b1));
}
// fast activations via MUFU (validated rel_err-neutral in R12)
__device__ __forceinline__ float fsig(float x)  { return __fdividef(1.0f, 1.0f + __expf(-x)); }
__device__ __forceinline__ float ftanh(float x) { return 1.0f - 2.0f * __fdividef(1.0f, 1.0f + __expf(2.0f * x)); }

// ---------------- setup kernels (vectorized — validated in R12) ----------------
__global__ void init_state_kernel() {
    int i = blockIdx.x * 256 + threadIdx.x;     // 524288 u32 = both h buffers
    ((uint32_t*)g_h16)[i] = 0u;
    if (i == 0) { g_cnt = 0; g_gen = 0; }
}

// interleaved bias: n' = 4u + gate
__global__ void bias_kernel(const float* __restrict__ b_ih, const float* __restrict__ b_hh) {
    int n_ = blockIdx.x * 256 + threadIdx.x;
    int gate = n_ & 3, j = n_ >> 2;
    g_bias[n_] = b_ih[gate * HIDD + j] + b_hh[gate * HIDD + j];
}

// W'g row n' = 4u+gate : [Wih(512) | Whh(1024)] fp16 (4 elems/thread)
__global__ void conv_wg_kernel(const float* __restrict__ W_ih, const float* __restrict__ W_hh) {
    int idx = blockIdx.x * 256 + threadIdx.x;   // NG*KIN/4
    int n_ = idx / (KIN / 4), k4 = (idx - n_ * (KIN / 4)) * 4;
    int gate = n_ & 3, j = n_ >> 2;
    int orig = gate * HIDD + j;
    float4 w = (k4 < EMBD) ? *(const float4*)&W_ih[(size_t)orig * EMBD + k4]
                           : *(const float4*)&W_hh[(size_t)orig * HIDD + (k4 - EMBD)];
    __half2 h0 = __floats2half2_rn(w.x, w.y);
    __half2 h1 = __floats2half2_rn(w.z, w.w);
    *(uint2*)&g_Wg[(size_t)n_ * KIN + k4] = make_uint2(*(uint32_t*)&h0, *(uint32_t*)&h1);
}

__global__ void conv_wo_kernel(const float* __restrict__ W_out) {
    int idx = blockIdx.x * 256 + threadIdx.x;   // NOUT*HIDD/4
    float4 w = *(const float4*)&W_out[(size_t)idx * 4];
    __half2 h0 = __floats2half2_rn(w.x, w.y);
    __half2 h1 = __floats2half2_rn(w.z, w.w);
    *(uint2*)&g_Wo[(size_t)idx * 4] = make_uint2(*(uint32_t*)&h0, *(uint32_t*)&h1);
}

__global__ void emb_precompute_kernel(const int* __restrict__ tok, const float* __restrict__ emb) {
    size_t idx = (size_t)blockIdx.x * 256 + threadIdx.x;   // TT*BB*EMBD/4
    int t = (int)(idx / (BB * EMBD / 4));
    int rem = (int)(idx - (size_t)t * (BB * EMBD / 4));
    int b = rem / (EMBD / 4), k4 = (rem - b * (EMBD / 4)) * 4;
    float4 v = *(const float4*)&emb[(size_t)tok[b * TT + t] * EMBD + k4];
    __half2 h0 = __floats2half2_rn(v.x, v.y);
    __half2 h1 = __floats2half2_rn(v.z, v.w);
    *(uint2*)&g_emb16[((size_t)t * BB + b) * EMBD + k4] = make_uint2(*(uint32_t*)&h0, *(uint32_t*)&h1);
}

// ---------------- persistent LSTM kernel: all 64 steps, 512 threads ----------------
// CTA (bn, bm): batch rows [bm*128,+128), interleaved gate cols [bn*128,+128) = units [bn*32,+32).
// 16 warps (4x4), warp tile 32x32 -> 4 warps/SMSP for latency hiding.
// c kept in registers across all steps. R11 barrier structure (wait+arrive at end of step).
__global__ __launch_bounds__(512, 1) void lstm_persistent_kernel() {
    extern __shared__ char dyn[];
    const uint32_t sbase = (smem_u32(dyn) + 127u) & ~127u;
    __half* hs = (__half*)(dyn + (sbase - smem_u32(dyn)));   // h stage = stage-0 region

    const int tid  = threadIdx.x;
    const int wid  = tid >> 5, lane = tid & 31;
    const int m0 = blockIdx.y * 128, n0 = blockIdx.x * 128;
    const int w_m = (wid >> 2) * 32;   // 0..96
    const int w_n = (wid & 3) * 32;    // 0..96

    // loader mapping: 512 threads, 2 x 16B segments per tile each
    const int lr  = tid >> 3;          // 0..63
    const int lsB = (tid & 7) * 16;

    // ldmatrix lane offsets (pre-swizzle)
    const int q  = lane >> 3;
    const int r8 = lane & 7;
    const uint32_t arow = (uint32_t)(w_m + (q & 1) * 8 + r8);
    const uint32_t akb  = (uint32_t)((q >> 1) * 16);
    const uint32_t brow = (uint32_t)(w_n + (q >> 1) * 8 + r8);
    const uint32_t bkb  = (uint32_t)((q & 1) * 16);

    // per-thread bias (constant across steps)
    const int lcol = (lane & 3) * 2;
    float bj0[4], bj1[4];
#pragma unroll
    for (int nj = 0; nj < 4; nj++) {
        int col = n0 + w_n + nj * 8 + lcol;
        bj0[nj] = g_bias[col];
        bj1[nj] = g_bias[col + 1];
    }

    const int lrow = lane >> 2;
    const bool evenlane = (lane & 1) == 0;
    const int ul_base = (w_n >> 2) + ((lane & 3) >> 1);   // + nj*2

    float c_reg[2][4];
#pragma unroll
    for (int i = 0; i < 2; i++)
#pragma unroll
        for (int j = 0; j < 4; j++) c_reg[i][j] = 0.0f;

    for (int t = 0; t < TT; t++) {
        const __half* Ah = g_h16[t & 1];

        auto issue = [&](int kc) {
            const uint32_t st = sbase + (kc % 3) * 32768;
            const __half* ag;
            size_t klda;
            if (kc < 8) {
                ag = g_emb16 + ((size_t)t * BB + (m0 + lr)) * EMBD + kc * 64 + (lsB >> 1);
                klda = EMBD;
            } else {
                ag = Ah + (size_t)(m0 + lr) * HIDD + (kc - 8) * 64 + (lsB >> 1);
                klda = HIDD;
            }
            const __half* bg = g_Wg + (size_t)(n0 + lr) * KIN + kc * 64 + (lsB >> 1);
#pragma unroll
            for (int i = 0; i < 2; i++) {
                uint32_t off = (uint32_t)(lr + i * 64) * 128u + (uint32_t)lsB;
                uint32_t sw  = off ^ ((off >> 3) & 0x70u);
                cp_async16(st + sw, ag + (size_t)i * 64 * klda);
                cp_async16(st + 16384 + sw, bg + (size_t)i * 64 * KIN);
            }
            cp_commit();
        };

        float acc[2][4][4];
#pragma unroll
        for (int i = 0; i < 2; i++)
#pragma unroll
            for (int j = 0; j < 4; j++)
#pragma unroll
                for (int v = 0; v < 4; v++) acc[i][j][v] = 0.0f;

        issue(0);
        issue(1);

        for (int kc = 0; kc < NCHUNK_G; kc++) {
            if (kc + 1 < NCHUNK_G) asm volatile("cp.async.wait_group 1;" ::: "memory");
            else                   asm volatile("cp.async.wait_group 0;" ::: "memory");
            __syncthreads();
            if (kc + 2 < NCHUNK_G) issue(kc + 2);

            const uint32_t stA = sbase + (kc % 3) * 32768;
            const uint32_t stB = stA + 16384;

#pragma unroll
            for (int kk = 0; kk < 4; kk++) {
                uint32_t afr[2][4];
#pragma unroll
                for (int mi = 0; mi < 2; mi++) {
                    uint32_t off = (arow + mi * 16) * 128u + kk * 32u + akb;
                    ldsm_x4(afr[mi], stA + (off ^ ((off >> 3) & 0x70u)));
                }
                uint32_t bfr[2][4];
#pragma unroll
                for (int nj2 = 0; nj2 < 2; nj2++) {
                    uint32_t off = (brow + nj2 * 16) * 128u + kk * 32u + bkb;
                    ldsm_x4(bfr[nj2], stB + (off ^ ((off >> 3) & 0x70u)));
                }
#pragma unroll
                for (int mi = 0; mi < 2; mi++)
#pragma unroll
                    for (int nj = 0; nj < 4; nj++)
                        mma16816(acc[mi][nj], afr[mi],
                                 bfr[nj >> 1][(nj & 1) * 2], bfr[nj >> 1][(nj & 1) * 2 + 1]);
            }
        }

        // ----- fused LSTM epilogue (pairing validated R8/R11) -----
#pragma unroll
        for (int mi = 0; mi < 2; mi++) {
#pragma unroll
            for (int nj = 0; nj < 4; nj++) {
                float a0 = acc[mi][nj][0] + bj0[nj];
                float a1 = acc[mi][nj][1] + bj1[nj];
                float a2 = acc[mi][nj][2] + bj0[nj];
                float a3 = acc[mi][nj][3] + bj1[nj];
                float p0 = __shfl_xor_sync(0xffffffffu, a0, 1);
                float p1 = __shfl_xor_sync(0xffffffffu, a1, 1);
                float p2 = __shfl_xor_sync(0xffffffffu, a2, 1);
                float p3 = __shfl_xor_sync(0xffffffffu, a3, 1);
                float i_, f_, g_, o_;
                int bl;
                if (evenlane) { i_ = a0; f_ = a1; g_ = p0; o_ = p1; bl = w_m + mi * 16 + lrow; }
                else          { i_ = p2; f_ = p3; g_ = a2; o_ = a3; bl = w_m + mi * 16 + lrow + 8; }
                int ul = ul_base + nj * 2;
                i_ = fsig(i_);
                f_ = fsig(f_);
                g_ = ftanh(g_);
                o_ = fsig(o_);
                float cn = f_ * c_reg[mi][nj] + i_ * g_;
                c_reg[mi][nj] = cn;
                hs[bl * 32 + ul] = __float2half(o_ * ftanh(cn));
            }
        }
        __syncthreads();

        // coalesced h store: 128 rows x 32 halves -> g_h16[(t+1)&1]  (512 uint4, 1/thread)
        __half* hdst = g_h16[(t + 1) & 1];
        {
            int row = tid >> 2, seg = tid & 3;
            uint4 v = ((const uint4*)hs)[tid];
            *(uint4*)(hdst + (size_t)(m0 + row) * HIDD + (n0 >> 2) + seg * 8) = v;
        }

        // ----- grid barrier (R11 structure) -----
        __syncthreads();
        if (tid == 0) {
            __threadfence();
            if (atomicAdd(&g_cnt, 1u) == NCTA - 1) {
                g_cnt = 0;
                __threadfence();
                g_gen = (unsigned)(t + 1);
            } else {
                while (g_gen < (unsigned)(t + 1)) __nanosleep(64);
                __threadfence();
            }
        }
        __syncthreads();
    }
}

// ---------------- output projection GEMM (256 threads, R11-proven) ----------------
__global__ __launch_bounds__(256, 1) void out_gemm(float* __restrict__ Cout,
                                                   const float* __restrict__ biasO) {
    extern __shared__ char dyn[];
    const uint32_t sbase = (smem_u32(dyn) + 127u) & ~127u;

    const int tid  = threadIdx.x;
    const int wid  = tid >> 5, lane = tid & 31;
    const int m0 = blockIdx.y * 128, n0 = blockIdx.x * 128;
    const int w_m = (wid >> 2) * 64;
    const int w_n = (wid & 3) * 32;

    const int lr  = tid >> 3;
    const int lsB = (tid & 7) * 16;
    const __half* Ah = g_h16[0];   // final h after 64 steps
    auto issue = [&](int kc) {
        const uint32_t st = sbase + (kc % 3) * 32768;
        const __half* ag = Ah + (size_t)(m0 + lr) * HIDD + kc * 64 + (lsB >> 1);
        const __half* bg = g_Wo + (size_t)(n0 + lr) * HIDD + kc * 64 + (lsB >> 1);
#pragma unroll
        for (int i = 0; i < 4; i++) {
            uint32_t off = (uint32_t)(lr + i * 32) * 128u + (uint32_t)lsB;
            uint32_t sw  = off ^ ((off >> 3) & 0x70u);
            cp_async16(st + sw, ag + (size_t)i * 32 * HIDD);
            cp_async16(st + 16384 + sw, bg + (size_t)i * 32 * HIDD);
        }
        cp_commit();
    };

    const int q  = lane >> 3;
    const int r8 = lane & 7;
    const uint32_t arow = (uint32_t)(w_m + (q & 1) * 8 + r8);
    const uint32_t akb  = (uint32_t)((q >> 1) * 16);
    const uint32_t brow = (uint32_t)(w_n + (q >> 1) * 8 + r8);
    const uint32_t bkb  = (uint32_t)((q & 1) * 16);

    float acc[4][4][4];
#pragma unroll
    for (int i = 0; i < 4; i++)
#pragma unroll
        for (int j = 0; j < 4; j++)
#pragma unroll
            for (int v = 0; v < 4; v++) acc[i][j][v] = 0.0f;

    issue(0);
    issue(1);

    for (int kc = 0; kc < NCHUNK_O; kc++) {
        if (kc + 1 < NCHUNK_O) asm volatile("cp.async.wait_group 1;" ::: "memory");
        else                   asm volatile("cp.async.wait_group 0;" ::: "memory");
        __syncthreads();
        if (kc + 2 < NCHUNK_O) issue(kc + 2);

        const uint32_t stA = sbase + (kc % 3) * 32768;
        const uint32_t stB = stA + 16384;

#pragma unroll
        for (int kk = 0; kk < 4; kk++) {
            uint32_t afr[4][4];
#pragma unroll
            for (int mi = 0; mi < 4; mi++) {
                uint32_t off = (arow + mi * 16) * 128u + kk * 32u + akb;
                ldsm_x4(afr[mi], stA + (off ^ ((off >> 3) & 0x70u)));
            }
            uint32_t bfr[2][4];
#pragma unroll
            for (int nj2 = 0; nj2 < 2; nj2++) {
                uint32_t off = (brow + nj2 * 16) * 128u + kk * 32u + bkb;
                ldsm_x4(bfr[nj2], stB + (off ^ ((off >> 3) & 0x70u)));
            }
#pragma unroll
            for (int mi = 0; mi < 4; mi++)
#pragma unroll
                for (int nj = 0; nj < 4; nj++)
                    mma16816(acc[mi][nj], afr[mi],
                             bfr[nj >> 1][(nj & 1) * 2], bfr[nj >> 1][(nj & 1) * 2 + 1]);
        }
    }

    const int lrow = lane >> 2;
    const int lcol = (lane & 3) * 2;
#pragma unroll
    for (int mi = 0; mi < 4; mi++) {
#pragma unroll
        for (int nj = 0; nj < 4; nj++) {
            int row0 = m0 + w_m + mi * 16 + lrow;
            int col  = n0 + w_n + nj * 8 + lcol;
            float b0 = __ldg(&biasO[col]), b1 = __ldg(&biasO[col + 1]);
            *(float2*)&Cout[(size_t)row0 * NOUT + col] =
                make_float2(acc[mi][nj][0] + b0, acc[mi][nj][1] + b1);
            *(float2*)&Cout[(size_t)(row0 + 8) * NOUT + col] =
                make_float2(acc[mi][nj][2] + b0, acc[mi][nj][3] + b1);
        }
    }
}

// ---------------- launch ----------------
extern "C" void kernel_launch(void* const* d_in, const int* in_sizes, int n_in,
                              void* d_out, int out_size) {
    const int*   m     = (const int*)  d_in[0];
    const float* emb   = (const float*)d_in[1];
    const float* W_ih  = (const float*)d_in[2];
    const float* W_hh  = (const float*)d_in[3];
    const float* b_ih  = (const float*)d_in[4];
    const float* b_hh  = (const float*)d_in[5];
    const float* W_out = (const float*)d_in[6];
    const float* b_out = (const float*)d_in[7];
    float* out = (float*)d_out;

    cudaFuncSetAttribute(lstm_persistent_kernel, cudaFuncAttributeMaxDynamicSharedMemorySize, SMEM_DYN);
    cudaFuncSetAttribute(out_gemm, cudaFuncAttributeMaxDynamicSharedMemorySize, SMEM_DYN);

    init_state_kernel<<<(2 * BB * HIDD / 2) / 256, 256>>>();
    bias_kernel<<<NG / 256, 256>>>(b_ih, b_hh);
    conv_wg_kernel<<<(NG * KIN / 4) / 256, 256>>>(W_ih, W_hh);
    conv_wo_kernel<<<(NOUT * HIDD / 4) / 256, 256>>>(W_out);
    emb_precompute_kernel<<<(unsigned)(((size_t)TT * BB * EMBD / 4) / 256), 256>>>(m, emb);

    lstm_persistent_kernel<<<dim3(32, 4), 512, SMEM_DYN>>>();
    out_gemm<<<dim3(NOUT / 128, BB / 128), 256, SMEM_DYN>>>(out, b_out);
}

// round 15
// speedup vs baseline: 1.4442x; 1.0372x over previous
#include <cuda_runtime.h>
#include <cuda_fp16.h>
#include <math.h>
#include <stdint.h>

// ---------------- problem constants ----------------
#define BB    512
#define TT    64
#define EMBD  512
#define HIDD  1024
#define NG    4096
#define NOUT  2048
#define KIN   (EMBD + HIDD)     // 1536 (gates GEMM K: [x | h])
#define NCHUNK_G (KIN / 64)     // 24  (chunks 0..7 emb, 8..23 h)
#define NCHUNK_O (HIDD / 64)    // 16
#define SMEM_HS  (3 * 32768)            // h-stage region (8 KB) after 3 pipeline stages
#define SMEM_DYN (3 * 32768 + 8192 + 256)

// ---------------- persistent device scratch ----------------
__device__ float g_bias[NG];                                      // interleaved b_ih+b_hh
__device__ __align__(16) __half g_h16[2][BB * HIDD];              // h (fp16), ping-pong
__device__ __align__(16) __half g_emb16[(size_t)TT * BB * EMBD];  // x_t (fp16), all steps
__device__ __align__(16) __half g_Wg[(size_t)NG * KIN];           // gate-interleaved rows [Wih|Whh]
__device__ __align__(16) __half g_Wo[(size_t)NOUT * HIDD];
__device__ unsigned g_cnt4[4];                                    // per-bm barriers (32 CTAs each)
__device__ volatile unsigned g_gen4[4];

// ---------------- helpers ----------------
__device__ __forceinline__ uint32_t smem_u32(const void* p) {
    uint32_t a;
    asm("{ .reg .u64 t; cvta.to.shared.u64 t, %1; cvt.u32.u64 %0, t; }" : "=r"(a) : "l"(p));
    return a;
}
__device__ __forceinline__ void cp_async16(uint32_t dst, const void* src) {
    asm volatile("cp.async.cg.shared.global [%0], [%1], 16;" :: "r"(dst), "l"(src));
}
__device__ __forceinline__ void cp_commit() {
    asm volatile("cp.async.commit_group;" ::: "memory");
}
__device__ __forceinline__ void ldsm_x4(uint32_t* r, uint32_t addr) {
    asm volatile("ldmatrix.sync.aligned.m8n8.x4.shared.b16 {%0,%1,%2,%3}, [%4];"
                 : "=r"(r[0]), "=r"(r[1]), "=r"(r[2]), "=r"(r[3]) : "r"(addr));
}
__device__ __forceinline__ void mma16816(float* d, const uint32_t* a, uint32_t b0, uint32_t b1) {
    asm volatile(
        "mma.sync.aligned.m16n8k16.row.col.f32.f16.f16.f32 "
        "{%0,%1,%2,%3}, {%4,%5,%6,%7}, {%8,%9}, {%0,%1,%2,%3};"
        : "+f"(d[0]), "+f"(d[1]), "+f"(d[2]), "+f"(d[3])
        : "r"(a[0]), "r"(a[1]), "r"(a[2]), "r"(a[3]), "r"(b0), "r"(b1));
}
// fast activations via MUFU (validated rel_err-neutral R12/R13)
__device__ __forceinline__ float fsig(float x)  { return __fdividef(1.0f, 1.0f + __expf(-x)); }
__device__ __forceinline__ float ftanh(float x) { return 1.0f - 2.0f * __fdividef(1.0f, 1.0f + __expf(2.0f * x)); }

// ---------------- fused setup kernel ----------------
#define WG_BLK   6144   // NG*KIN/4/256
#define WO_BLK   2048   // NOUT*HIDD/4/256
#define INIT_BLK 512    // 131072 uint4 / 256
#define BIAS_BLK 16     // NG/256
__global__ void setup_kernel(const float* __restrict__ W_ih, const float* __restrict__ W_hh,
                             const float* __restrict__ W_out,
                             const float* __restrict__ b_ih, const float* __restrict__ b_hh) {
    int bx = blockIdx.x;
    if (bx < WG_BLK) {
        int idx = bx * 256 + threadIdx.x;           // NG*KIN/4
        int n_ = idx / (KIN / 4), k4 = (idx - n_ * (KIN / 4)) * 4;
        int gate = n_ & 3, j = n_ >> 2;
        int orig = gate * HIDD + j;
        float4 w = (k4 < EMBD) ? *(const float4*)&W_ih[(size_t)orig * EMBD + k4]
                               : *(const float4*)&W_hh[(size_t)orig * HIDD + (k4 - EMBD)];
        __half2 h0 = __floats2half2_rn(w.x, w.y);
        __half2 h1 = __floats2half2_rn(w.z, w.w);
        *(uint2*)&g_Wg[(size_t)n_ * KIN + k4] = make_uint2(*(uint32_t*)&h0, *(uint32_t*)&h1);
    } else if (bx < WG_BLK + WO_BLK) {
        int idx = (bx - WG_BLK) * 256 + threadIdx.x;   // NOUT*HIDD/4
        float4 w = *(const float4*)&W_out[(size_t)idx * 4];
        __half2 h0 = __floats2half2_rn(w.x, w.y);
        __half2 h1 = __floats2half2_rn(w.z, w.w);
        *(uint2*)&g_Wo[(size_t)idx * 4] = make_uint2(*(uint32_t*)&h0, *(uint32_t*)&h1);
    } else if (bx < WG_BLK + WO_BLK + INIT_BLK) {
        int i = (bx - WG_BLK - WO_BLK) * 256 + threadIdx.x;   // 131072 uint4
        ((uint4*)g_h16)[i] = make_uint4(0u, 0u, 0u, 0u);
        if (i < 4) { g_cnt4[i] = 0u; g_gen4[i] = 0u; }
    } else {
        int n_ = (bx - WG_BLK - WO_BLK - INIT_BLK) * 256 + threadIdx.x;
        int gate = n_ & 3, j = n_ >> 2;
        g_bias[n_] = b_ih[gate * HIDD + j] + b_hh[gate * HIDD + j];
    }
}

// Precompute x_t (fp16) for all steps (4 elems/thread)
__global__ void emb_precompute_kernel(const int* __restrict__ tok, const float* __restrict__ emb) {
    size_t idx = (size_t)blockIdx.x * 256 + threadIdx.x;   // TT*BB*EMBD/4
    int t = (int)(idx / (BB * EMBD / 4));
    int rem = (int)(idx - (size_t)t * (BB * EMBD / 4));
    int b = rem / (EMBD / 4), k4 = (rem - b * (EMBD / 4)) * 4;
    float4 v = *(const float4*)&emb[(size_t)tok[b * TT + t] * EMBD + k4];
    __half2 h0 = __floats2half2_rn(v.x, v.y);
    __half2 h1 = __floats2half2_rn(v.z, v.w);
    *(uint2*)&g_emb16[((size_t)t * BB + b) * EMBD + k4] = make_uint2(*(uint32_t*)&h0, *(uint32_t*)&h1);
}

// ---------------- persistent LSTM kernel: all 64 steps, 512 threads ----------------
// 16 warps (4x4), warp tile 32x32. c in registers across steps.
// Per-bm (32-CTA) barriers; cross-step load pipelining; gen-wait folded into kc==6.
__global__ __launch_bounds__(512, 1) void lstm_persistent_kernel() {
    extern __shared__ char dyn[];
    const uint32_t sbase = (smem_u32(dyn) + 127u) & ~127u;
    __half* hs = (__half*)(dyn + (sbase - smem_u32(dyn)) + SMEM_HS);   // dedicated region

    const int tid  = threadIdx.x;
    const int wid  = tid >> 5, lane = tid & 31;
    const int bmid = blockIdx.y;
    const int m0 = blockIdx.y * 128, n0 = blockIdx.x * 128;
    const int w_m = (wid >> 2) * 32;
    const int w_n = (wid & 3) * 32;

    // loader mapping: 512 threads, 2 x 16B segments per tile each
    const int lr  = tid >> 3;          // 0..63
    const int lsB = (tid & 7) * 16;

    // ldmatrix lane offsets (pre-swizzle)
    const int q  = lane >> 3;
    const int r8 = lane & 7;
    const uint32_t arow = (uint32_t)(w_m + (q & 1) * 8 + r8);
    const uint32_t akb  = (uint32_t)((q >> 1) * 16);
    const uint32_t brow = (uint32_t)(w_n + (q >> 1) * 8 + r8);
    const uint32_t bkb  = (uint32_t)((q & 1) * 16);

    // per-thread bias (constant across steps)
    const int lcol = (lane & 3) * 2;
    float bj0[4], bj1[4];
#pragma unroll
    for (int nj = 0; nj < 4; nj++) {
        int col = n0 + w_n + nj * 8 + lcol;
        bj0[nj] = g_bias[col];
        bj1[nj] = g_bias[col + 1];
    }

    const int lrow = lane >> 2;
    const bool evenlane = (lane & 1) == 0;
    const int ul_base = (w_n >> 2) + ((lane & 3) >> 1);   // + nj*2

    float c_reg[2][4];
#pragma unroll
    for (int i = 0; i < 2; i++)
#pragma unroll
        for (int j = 0; j < 4; j++) c_reg[i][j] = 0.0f;

    // issue chunk kcc of step tt (stage = kcc % 3)
    auto issue = [&](int kcc, int tt) {
        const uint32_t st = sbase + (kcc % 3) * 32768;
        const __half* ag;
        size_t klda;
        if (kcc < 8) {
            ag = g_emb16 + ((size_t)tt * BB + (m0 + lr)) * EMBD + kcc * 64 + (lsB >> 1);
            klda = EMBD;
        } else {
            ag = g_h16[tt & 1] + (size_t)(m0 + lr) * HIDD + (kcc - 8) * 64 + (lsB >> 1);
            klda = HIDD;
        }
        const __half* bg = g_Wg + (size_t)(n0 + lr) * KIN + kcc * 64 + (lsB >> 1);
#pragma unroll
        for (int i = 0; i < 2; i++) {
            uint32_t off = (uint32_t)(lr + i * 64) * 128u + (uint32_t)lsB;
            uint32_t sw  = off ^ ((off >> 3) & 0x70u);
            cp_async16(st + sw, ag + (size_t)i * 64 * klda);
            cp_async16(st + 16384 + sw, bg + (size_t)i * 64 * KIN);
        }
        cp_commit();
    };

    issue(0, 0);
    issue(1, 0);

    for (int t = 0; t < TT; t++) {
        const bool has_next = (t < TT - 1);

        float acc[2][4][4];
#pragma unroll
        for (int i = 0; i < 2; i++)
#pragma unroll
            for (int j = 0; j < 4; j++)
#pragma unroll
                for (int v = 0; v < 4; v++) acc[i][j][v] = 0.0f;

        for (int kc = 0; kc < NCHUNK_G; kc++) {
            // pending groups before wait: {kc, kc+1} (cross-step keeps pipeline full)
            if (kc < NCHUNK_G - 1 || has_next)
                asm volatile("cp.async.wait_group 1;" ::: "memory");
            else
                asm volatile("cp.async.wait_group 0;" ::: "memory");

            if (kc == 6) {
                // deferred gen-wait: h(t) (written end of step t-1) must be ready before issue(8)
                if (tid == 0) {
                    while (g_gen4[bmid] < (unsigned)t) __nanosleep(32);
                    __threadfence();
                }
            }
            __syncthreads();

            const int nx = kc + 2;
            if (nx < NCHUNK_G)      issue(nx, t);
            else if (has_next)      issue(nx - NCHUNK_G, t + 1);   // x-chunks 0,1 of next step

            const uint32_t stA = sbase + (kc % 3) * 32768;
            const uint32_t stB = stA + 16384;

#pragma unroll
            for (int kk = 0; kk < 4; kk++) {
                uint32_t afr[2][4];
#pragma unroll
                for (int mi = 0; mi < 2; mi++) {
                    uint32_t off = (arow + mi * 16) * 128u + kk * 32u + akb;
                    ldsm_x4(afr[mi], stA + (off ^ ((off >> 3) & 0x70u)));
                }
                uint32_t bfr[2][4];
#pragma unroll
                for (int nj2 = 0; nj2 < 2; nj2++) {
                    uint32_t off = (brow + nj2 * 16) * 128u + kk * 32u + bkb;
                    ldsm_x4(bfr[nj2], stB + (off ^ ((off >> 3) & 0x70u)));
                }
#pragma unroll
                for (int mi = 0; mi < 2; mi++)
#pragma unroll
                    for (int nj = 0; nj < 4; nj++)
                        mma16816(acc[mi][nj], afr[mi],
                                 bfr[nj >> 1][(nj & 1) * 2], bfr[nj >> 1][(nj & 1) * 2 + 1]);
            }
        }

        // ----- fused LSTM epilogue (overlaps next step's c0/c1 loads) -----
#pragma unroll
        for (int mi = 0; mi < 2; mi++) {
#pragma unroll
            for (int nj = 0; nj < 4; nj++) {
                float a0 = acc[mi][nj][0] + bj0[nj];
                float a1 = acc[mi][nj][1] + bj1[nj];
                float a2 = acc[mi][nj][2] + bj0[nj];
                float a3 = acc[mi][nj][3] + bj1[nj];
                float p0 = __shfl_xor_sync(0xffffffffu, a0, 1);
                float p1 = __shfl_xor_sync(0xffffffffu, a1, 1);
                float p2 = __shfl_xor_sync(0xffffffffu, a2, 1);
                float p3 = __shfl_xor_sync(0xffffffffu, a3, 1);
                float i_, f_, g_, o_;
                int bl;
                if (evenlane) { i_ = a0; f_ = a1; g_ = p0; o_ = p1; bl = w_m + mi * 16 + lrow; }
                else          { i_ = p2; f_ = p3; g_ = a2; o_ = a3; bl = w_m + mi * 16 + lrow + 8; }
                int ul = ul_base + nj * 2;
                i_ = fsig(i_);
                f_ = fsig(f_);
                g_ = ftanh(g_);
                o_ = fsig(o_);
                float cn = f_ * c_reg[mi][nj] + i_ * g_;
                c_reg[mi][nj] = cn;
                hs[bl * 32 + ul] = __float2half(o_ * ftanh(cn));
            }
        }
        __syncthreads();

        // coalesced h store: 128 rows x 32 halves -> g_h16[(t+1)&1]  (512 uint4, 1/thread)
        __half* hdst = g_h16[(t + 1) & 1];
        {
            int row = tid >> 2, seg = tid & 3;
            uint4 v = ((const uint4*)hs)[tid];
            *(uint4*)(hdst + (size_t)(m0 + row) * HIDD + (n0 >> 2) + seg * 8) = v;
        }
        __syncthreads();

        // per-bm arrive (wait deferred into next step's kc==6)
        if (tid == 0) {
            __threadfence();
            if (atomicAdd(&g_cnt4[bmid], 1u) == 31u) {
                g_cnt4[bmid] = 0u;
                __threadfence();
                g_gen4[bmid] = (unsigned)(t + 1);
            }
        }
    }
}

// ---------------- output projection GEMM (256 threads, R11-proven) ----------------
__global__ __launch_bounds__(256, 1) void out_gemm(float* __restrict__ Cout,
                                                   const float* __restrict__ biasO) {
    extern __shared__ char dyn[];
    const uint32_t sbase = (smem_u32(dyn) + 127u) & ~127u;

    const int tid  = threadIdx.x;
    const int wid  = tid >> 5, lane = tid & 31;
    const int m0 = blockIdx.y * 128, n0 = blockIdx.x * 128;
    const int w_m = (wid >> 2) * 64;
    const int w_n = (wid & 3) * 32;

    const int lr  = tid >> 3;
    const int lsB = (tid & 7) * 16;
    const __half* Ah = g_h16[0];   // final h after 64 steps
    auto issue = [&](int kc) {
        const uint32_t st = sbase + (kc % 3) * 32768;
        const __half* ag = Ah + (size_t)(m0 + lr) * HIDD + kc * 64 + (lsB >> 1);
        const __half* bg = g_Wo + (size_t)(n0 + lr) * HIDD + kc * 64 + (lsB >> 1);
#pragma unroll
        for (int i = 0; i < 4; i++) {
            uint32_t off = (uint32_t)(lr + i * 32) * 128u + (uint32_t)lsB;
            uint32_t sw  = off ^ ((off >> 3) & 0x70u);
            cp_async16(st + sw, ag + (size_t)i * 32 * HIDD);
            cp_async16(st + 16384 + sw, bg + (size_t)i * 32 * HIDD);
        }
        cp_commit();
    };

    const int q  = lane >> 3;
    const int r8 = lane & 7;
    const uint32_t arow = (uint32_t)(w_m + (q & 1) * 8 + r8);
    const uint32_t akb  = (uint32_t)((q >> 1) * 16);
    const uint32_t brow = (uint32_t)(w_n + (q >> 1) * 8 + r8);
    const uint32_t bkb  = (uint32_t)((q & 1) * 16);

    float acc[4][4][4];
#pragma unroll
    for (int i = 0; i < 4; i++)
#pragma unroll
        for (int j = 0; j < 4; j++)
#pragma unroll
            for (int v = 0; v < 4; v++) acc[i][j][v] = 0.0f;

    issue(0);
    issue(1);

    for (int kc = 0; kc < NCHUNK_O; kc++) {
        if (kc + 1 < NCHUNK_O) asm volatile("cp.async.wait_group 1;" ::: "memory");
        else                   asm volatile("cp.async.wait_group 0;" ::: "memory");
        __syncthreads();
        if (kc + 2 < NCHUNK_O) issue(kc + 2);

        const uint32_t stA = sbase + (kc % 3) * 32768;
        const uint32_t stB = stA + 16384;

#pragma unroll
        for (int kk = 0; kk < 4; kk++) {
            uint32_t afr[4][4];
#pragma unroll
            for (int mi = 0; mi < 4; mi++) {
                uint32_t off = (arow + mi * 16) * 128u + kk * 32u + akb;
                ldsm_x4(afr[mi], stA + (off ^ ((off >> 3) & 0x70u)));
            }
            uint32_t bfr[2][4];
#pragma unroll
            for (int nj2 = 0; nj2 < 2; nj2++) {
                uint32_t off = (brow + nj2 * 16) * 128u + kk * 32u + bkb;
                ldsm_x4(bfr[nj2], stB + (off ^ ((off >> 3) & 0x70u)));
            }
#pragma unroll
            for (int mi = 0; mi < 4; mi++)
#pragma unroll
                for (int nj = 0; nj < 4; nj++)
                    mma16816(acc[mi][nj], afr[mi],
                             bfr[nj >> 1][(nj & 1) * 2], bfr[nj >> 1][(nj & 1) * 2 + 1]);
        }
    }

    const int lrow = lane >> 2;
    const int lcol = (lane & 3) * 2;
#pragma unroll
    for (int mi = 0; mi < 4; mi++) {
#pragma unroll
        for (int nj = 0; nj < 4; nj++) {
            int row0 = m0 + w_m + mi * 16 + lrow;
            int col  = n0 + w_n + nj * 8 + lcol;
            float b0 = __ldg(&biasO[col]), b1 = __ldg(&biasO[col + 1]);
            *(float2*)&Cout[(size_t)row0 * NOUT + col] =
                make_float2(acc[mi][nj][0] + b0, acc[mi][nj][1] + b1);
            *(float2*)&Cout[(size_t)(row0 + 8) * NOUT + col] =
                make_float2(acc[mi][nj][2] + b0, acc[mi][nj][3] + b1);
        }
    }
}

// ---------------- launch ----------------
extern "C" void kernel_launch(void* const* d_in, const int* in_sizes, int n_in,
                              void* d_out, int out_size) {
    const int*   m     = (const int*)  d_in[0];
    const float* emb   = (const float*)d_in[1];
    const float* W_ih  = (const float*)d_in[2];
    const float* W_hh  = (const float*)d_in[3];
    const float* b_ih  = (const float*)d_in[4];
    const float* b_hh  = (const float*)d_in[5];
    const float* W_out = (const float*)d_in[6];
    const float* b_out = (const float*)d_in[7];
    float* out = (float*)d_out;

    cudaFuncSetAttribute(lstm_persistent_kernel, cudaFuncAttributeMaxDynamicSharedMemorySize, SMEM_DYN);
    cudaFuncSetAttribute(out_gemm, cudaFuncAttributeMaxDynamicSharedMemorySize, SMEM_DYN);

    setup_kernel<<<WG_BLK + WO_BLK + INIT_BLK + BIAS_BLK, 256>>>(W_ih, W_hh, W_out, b_ih, b_hh);
    emb_precompute_kernel<<<(unsigned)(((size_t)TT * BB * EMBD / 4) / 256), 256>>>(m, emb);

    lstm_persistent_kernel<<<dim3(32, 4), 512, SMEM_DYN>>>();
    out_gemm<<<dim3(NOUT / 128, BB / 128), 256, SMEM_DYN>>>(out, b_out);
}